// round 5
// baseline (speedup 1.0000x reference)
#include <cuda_runtime.h>
#include <cuda_bf16.h>
#include <cstdint>

#define BATCH 128
#define CH    128
#define NN    170
#define TT    12
#define XP    172          // f32 pitch for xs and ed tiles
#define ESP   176          // padded pitch of g_EsP

// shared memory layout (f32 words)
#define W_XS   0           // xs [128][172] = 22016 words (+32 slack)
#define W_ED   22048       // ed [170][172] = 29240 words (+64 slack)
#define SMEM_WORDS (22048 + 29240 + 64)          // 51352 words
#define SMEM_BYTES (SMEM_WORDS * 4)              // 205,408 B

static __device__ float g_EsP[CH * ESP + 64];    // padded/aligned E_s
static __device__ float g_Asum[NN * NN];         // batch-summed softmax

// ------------------------------------------------------- packed f32x2 helpers
typedef unsigned long long u64t;

__device__ __forceinline__ u64t splat2(float v) {
    u64t d; asm("mov.b64 %0, {%1, %1};" : "=l"(d) : "f"(v)); return d;
}
__device__ __forceinline__ void ffma2(u64t& c, u64t a, u64t b) {
    asm("fma.rn.f32x2 %0, %1, %2, %3;" : "=l"(c) : "l"(a), "l"(b), "l"(c));
}
__device__ __forceinline__ void unpack2(float& lo, float& hi, u64t v) {
    asm("mov.b64 {%0, %1}, %2;" : "=f"(lo), "=f"(hi) : "l"(v));
}
__device__ __forceinline__ float tanh_ap(float x) {
    float r; asm("tanh.approx.f32 %0, %1;" : "=f"(r) : "f"(x)); return r;
}

// ---------------------------------------------------------- K0: pad/align E_s
__global__ void k_prep(const float* __restrict__ Es) {
    int i = blockIdx.x * blockDim.x + threadIdx.x;
    if (i < CH * ESP) {
        int c = i / ESP, m = i - c * ESP;
        g_EsP[i] = (m < NN) ? Es[c * NN + m] : 0.0f;
    }
}

// ------------------------------------------------------------ fused per-batch
__global__ void __launch_bounds__(512, 1) k_fuse(const float* __restrict__ x) {
    extern __shared__ float sm[];
    float* xs = sm + W_XS;   // [128][172]
    float* ed = sm + W_ED;   // [170][172]  (E_d transposed: [m][n])
    __nv_bfloat16* sc = reinterpret_cast<__nv_bfloat16*>(sm);  // reuses xs after GEMM1
    const int tid = threadIdx.x;
    const int b = blockIdx.x;

    // ---- phase A: time reduction -> xs[c][n] (streaming loads, evict-first)
    const float* xb = x + (size_t)b * (CH * NN * TT);
    #pragma unroll 2
    for (int idx = tid; idx < CH * NN; idx += 512) {
        int c = idx / NN, n = idx - c * NN;
        const float4* p = reinterpret_cast<const float4*>(xb + (size_t)idx * TT);
        float4 v0 = __ldcs(p), v1 = __ldcs(p + 1), v2 = __ldcs(p + 2);
        float s = ((v0.x + v0.y) + (v0.z + v0.w))
                + ((v1.x + v1.y) + (v1.z + v1.w))
                + ((v2.x + v2.y) + (v2.z + v2.w));
        xs[c * XP + n] = s;
    }
    __syncthreads();

    // ---- GEMM1 (role-swapped, output pre-transposed):
    //      ed[m][n] = tanh( sum_c EsP[c][m] * xs[c][n] )
    const int grp = tid >> 8;
    const int gt  = tid & 255;
    const int tx = gt & 15, ty = gt >> 4;

    for (int t = grp; t < 9; t += 2) {
        const int tn = t % 3, tm = t / 3;
        const int bn = tn * 64 + tx * 4;   // n: xs col / output col
        const int am = tm * 64 + ty * 4;   // m: EsP col / output row
        u64t acc[4][2];
        #pragma unroll
        for (int i = 0; i < 4; i++) { acc[i][0] = 0ull; acc[i][1] = 0ull; }

        const float* ap = g_EsP + am;      // global, L2-resident
        const float* bp = xs + bn;         // smem
        #pragma unroll 4
        for (int c = 0; c < CH; c++) {
            float4 a4 = *reinterpret_cast<const float4*>(ap + c * ESP);
            ulonglong2 b2 = *reinterpret_cast<const ulonglong2*>(bp + c * XP);
            u64t s0 = splat2(a4.x), s1 = splat2(a4.y),
                 s2 = splat2(a4.z), s3 = splat2(a4.w);
            ffma2(acc[0][0], s0, b2.x); ffma2(acc[0][1], s0, b2.y);
            ffma2(acc[1][0], s1, b2.x); ffma2(acc[1][1], s1, b2.y);
            ffma2(acc[2][0], s2, b2.x); ffma2(acc[2][1], s2, b2.y);
            ffma2(acc[3][0], s3, b2.x); ffma2(acc[3][1], s3, b2.y);
        }

        if (bn < NN) {
            #pragma unroll
            for (int i = 0; i < 4; i++) {
                int m = am + i;
                if (m < NN) {
                    float a0, a1, a2, a3;
                    unpack2(a0, a1, acc[i][0]);
                    unpack2(a2, a3, acc[i][1]);
                    float4 v;
                    v.x = tanh_ap(a0); v.y = tanh_ap(a1);
                    v.z = tanh_ap(a2); v.w = tanh_ap(a3);
                    *reinterpret_cast<float4*>(ed + m * XP + bn) = v;
                }
            }
        }
    }
    __syncthreads();

    // ---- GEMM2: scores = relu(Ed @ Ed^T / sqrt(C)); symmetric, 6 of 9 tiles
    const int n0s[6] = {0, 64, 128, 0, 0, 64};
    const int k0s[6] = {0, 64, 128, 64, 128, 128};

    for (int t = grp; t < 6; t += 2) {
        const int n0 = n0s[t], k0 = k0s[t];
        const int an = n0 + ty * 4;
        const int bk = k0 + tx * 4;
        u64t acc[4][2];
        #pragma unroll
        for (int i = 0; i < 4; i++) { acc[i][0] = 0ull; acc[i][1] = 0ull; }

        const float* ap = ed + an;
        const float* bp = ed + bk;
        #pragma unroll 2
        for (int m = 0; m < NN; m++) {
            float4 a4 = *reinterpret_cast<const float4*>(ap + m * XP);
            ulonglong2 b2 = *reinterpret_cast<const ulonglong2*>(bp + m * XP);
            u64t s0 = splat2(a4.x), s1 = splat2(a4.y),
                 s2 = splat2(a4.z), s3 = splat2(a4.w);
            ffma2(acc[0][0], s0, b2.x); ffma2(acc[0][1], s0, b2.y);
            ffma2(acc[1][0], s1, b2.x); ffma2(acc[1][1], s1, b2.y);
            ffma2(acc[2][0], s2, b2.x); ffma2(acc[2][1], s2, b2.y);
            ffma2(acc[3][0], s3, b2.x); ffma2(acc[3][1], s3, b2.y);
        }

        const float scale = 0.08838834764831843f;  // 1/sqrt(128)
        #pragma unroll
        for (int i = 0; i < 4; i++) {
            int n = an + i;
            if (n >= NN) continue;
            float av[4];
            unpack2(av[0], av[1], acc[i][0]);
            unpack2(av[2], av[3], acc[i][1]);
            #pragma unroll
            for (int j = 0; j < 4; j++) {
                int k = bk + j;
                if (k >= NN) continue;
                float s = fmaxf(0.0f, av[j] * scale);
                __nv_bfloat16 h = __float2bfloat16(s);
                sc[n * XP + k] = h;
                if (n0 != k0) sc[k * XP + n] = h;   // symmetric counterpart
            }
        }
    }
    __syncthreads();

    // ---- row softmax (no max-pass: scores in [0, ~15.1]) + atomic accumulate
    const int wid = tid >> 5, lane = tid & 31;
    for (int n = wid; n < NN; n += 16) {
        const __nv_bfloat16* row = sc + n * XP;
        float ssum = 0.0f;
        for (int k = lane; k < NN; k += 32)
            ssum += __expf(__bfloat162float(row[k]));
        #pragma unroll
        for (int o = 16; o; o >>= 1)
            ssum += __shfl_xor_sync(0xffffffffu, ssum, o);
        float inv = 1.0f / ssum;
        for (int k = lane; k < NN; k += 32)
            atomicAdd(&g_Asum[n * NN + k],
                      __expf(__bfloat162float(row[k])) * inv);
    }
}

// --------------------------------- K3: threshold + self-restore (zero g_Asum)
__global__ void k_thresh(float* __restrict__ out) {
    int i = blockIdx.x * blockDim.x + threadIdx.x;
    if (i < NN * NN) {
        out[i] = (g_Asum[i] > 64.0f) ? 1.0f : 0.0f;  // mean > 0.5
        g_Asum[i] = 0.0f;  // restore for next (graph-replayed) run
    }
}

// ------------------------------------------------------------------- launcher
extern "C" void kernel_launch(void* const* d_in, const int* in_sizes, int n_in,
                              void* d_out, int out_size) {
    const float* x  = (const float*)d_in[0];   // [128,128,170,12] f32
    const float* Es = (const float*)d_in[1];   // [128,170] f32
    float* out = (float*)d_out;                // [170,170] f32

    cudaFuncSetAttribute(k_fuse, cudaFuncAttributeMaxDynamicSharedMemorySize, SMEM_BYTES);

    k_prep<<<(CH * ESP + 255) / 256, 256>>>(Es);
    k_fuse<<<BATCH, 512, SMEM_BYTES>>>(x);
    k_thresh<<<(NN * NN + 255) / 256, 256>>>(out);
}

// round 6
// speedup vs baseline: 1.1945x; 1.1945x over previous
#include <cuda_runtime.h>
#include <cuda_bf16.h>
#include <cstdint>

#define BATCH 128
#define CH    128
#define NN    170
#define TT    12
#define EDP   172          // g_Ed / ed / sc pitch (f32 words / bf16 elems)
#define XSP   88           // xs smem pitch per half
#define ESPW  88           // es smem pitch in u32 words (176 bf16)

// k_embed smem: xs f32 [128][88] (11264 w) + es bf16 [128][176] (11264 w) + slack
#define SMEM_E ((11264 + 11264 + 32) * 4)                  // 90,240 B -> 2 CTA/SM
// k_adj smem: ed f32 [170][172] (29240 w) + 64 slack + sc bf16 [170][172] (14620 w)
#define SMEM_A ((29240 + 64 + 14620) * 4)                  // 175,696 B

static __device__ __align__(16) float g_Ed[BATCH * NN * EDP];  // E_d^T: [b][m][n]
static __device__ float g_Asum[NN * NN];

// ------------------------------------------------------- packed f32x2 helpers
typedef unsigned long long u64t;

__device__ __forceinline__ u64t splat2(float v) {
    u64t d; asm("mov.b64 %0, {%1, %1};" : "=l"(d) : "f"(v)); return d;
}
__device__ __forceinline__ u64t splat2u(unsigned v) {     // f32 bit pattern in u32
    u64t d; asm("mov.b64 %0, {%1, %1};" : "=l"(d) : "r"(v)); return d;
}
__device__ __forceinline__ void ffma2(u64t& c, u64t a, u64t b) {
    asm("fma.rn.f32x2 %0, %1, %2, %3;" : "=l"(c) : "l"(a), "l"(b), "l"(c));
}
__device__ __forceinline__ void unpack2(float& lo, float& hi, u64t v) {
    asm("mov.b64 {%0, %1}, %2;" : "=f"(lo), "=f"(hi) : "l"(v));
}
__device__ __forceinline__ float tanh_ap(float x) {
    float r; asm("tanh.approx.f32 %0, %1;" : "=f"(r) : "f"(x)); return r;
}

// ---------------------------------------------------------------- x loader
template <int NW>
__device__ __forceinline__ void load_x(const float* __restrict__ xb, float* xs,
                                       int n0g, int tid) {
    #pragma unroll 4
    for (int idx = tid; idx < CH * NW; idx += 256) {
        int c = idx / NW, n = idx - c * NW;
        const float4* p = reinterpret_cast<const float4*>(
            xb + ((size_t)c * NN + n0g + n) * TT);
        float4 v0 = __ldcs(p), v1 = __ldcs(p + 1), v2 = __ldcs(p + 2);
        xs[c * XSP + n] = ((v0.x + v0.y) + (v0.z + v0.w))
                        + ((v1.x + v1.y) + (v1.z + v1.w))
                        + ((v2.x + v2.y) + (v2.z + v2.w));
    }
}

// ---------------------- K1: t-reduce + GEMM1 (output pre-transposed) + tanh
// grid (128, 2): CTA (b, h) computes ed[m][n] = tanh(sum_c Es[c][m] xs[c][n])
// for n in its 88/82-column half; stores g_Ed[b][m][n] (pads n=170,171 get 0).
__global__ void __launch_bounds__(256, 2) k_embed(const float* __restrict__ x,
                                                  const float* __restrict__ Es) {
    extern __shared__ float sm[];
    float* xs = sm;                                   // [128][88]
    unsigned* es = reinterpret_cast<unsigned*>(sm + CH * XSP);  // bf16x2 [128][88w]
    const int tid = threadIdx.x;
    const int b = blockIdx.x, h = blockIdx.y;
    const int n0g = h * 88;

    // stage Es as packed bf16 pairs: es[c][mp] = {Es[c][2mp], Es[c][2mp+1]}
    for (int i = tid; i < CH * ESPW; i += 256) {
        int c = i / ESPW, mp = i - c * ESPW;
        int m0 = mp * 2;
        float f0 = 0.f, f1 = 0.f;
        if (m0 < NN) {   // m0 even, NN even -> float2-aligned pair load
            float2 e = *reinterpret_cast<const float2*>(Es + c * NN + m0);
            f0 = e.x; f1 = e.y;
        }
        __nv_bfloat162 hh = __floats2bfloat162_rn(f0, f1);
        es[i] = *reinterpret_cast<unsigned*>(&hh);
    }

    // time reduction into xs (+ zero pad cols for h=1)
    const float* xb = x + (size_t)b * (CH * NN * TT);
    if (h == 0) load_x<88>(xb, xs, n0g, tid);
    else {
        load_x<82>(xb, xs, n0g, tid);
        for (int i = tid; i < CH * 6; i += 256) {
            int c = i / 6, j = i - c * 6;
            xs[c * XSP + 82 + j] = 0.0f;
        }
    }
    __syncthreads();

    // GEMM1: exact-cover 4x4 cells over [176 m] x [88 n] = 44*22 = 968 cells
    float* Edb = g_Ed + (size_t)b * (NN * EDP);
    for (int cell = tid; cell < 968; cell += 256) {
        const int smi = cell / 22, snj = cell - smi * 22;
        const int am = smi * 4;          // m base (Es side, splat)
        const int bn = snj * 4;          // n base (xs side, pairs)
        u64t acc[4][2];
        #pragma unroll
        for (int i = 0; i < 4; i++) { acc[i][0] = 0ull; acc[i][1] = 0ull; }

        const unsigned* ep = es + (am >> 1);
        const float* bp = xs + bn;
        #pragma unroll 4
        for (int c = 0; c < CH; c++) {
            uint2 ev = *reinterpret_cast<const uint2*>(ep + c * ESPW);
            ulonglong2 b2 = *reinterpret_cast<const ulonglong2*>(bp + c * XSP);
            u64t s0 = splat2u(ev.x << 16);
            u64t s1 = splat2u(ev.x & 0xFFFF0000u);
            u64t s2 = splat2u(ev.y << 16);
            u64t s3 = splat2u(ev.y & 0xFFFF0000u);
            ffma2(acc[0][0], s0, b2.x); ffma2(acc[0][1], s0, b2.y);
            ffma2(acc[1][0], s1, b2.x); ffma2(acc[1][1], s1, b2.y);
            ffma2(acc[2][0], s2, b2.x); ffma2(acc[2][1], s2, b2.y);
            ffma2(acc[3][0], s3, b2.x); ffma2(acc[3][1], s3, b2.y);
        }

        const int ng = n0g + bn;
        if (ng <= EDP - 4) {             // skip h=1 strip beyond pitch (172..175)
            #pragma unroll
            for (int i = 0; i < 4; i++) {
                int m = am + i;
                if (m < NN) {
                    float a0, a1, a2, a3;
                    unpack2(a0, a1, acc[i][0]);
                    unpack2(a2, a3, acc[i][1]);
                    float4 v;
                    v.x = tanh_ap(a0); v.y = tanh_ap(a1);
                    v.z = tanh_ap(a2); v.w = tanh_ap(a3);
                    *reinterpret_cast<float4*>(Edb + m * EDP + ng) = v;
                }
            }
        }
    }
}

// ---------------- K2: GEMM2 (symmetric triangle) + softmax + atomic accumulate
__global__ void __launch_bounds__(512, 1) k_adj() {
    extern __shared__ float sm[];
    float* ed = sm;                                        // [170][172] (= E_d^T)
    __nv_bfloat16* sc = reinterpret_cast<__nv_bfloat16*>(sm + 29240 + 64);
    const int tid = threadIdx.x;
    const int b = blockIdx.x;

    // coalesced copy-in (already [m][n] layout)
    {
        const uint4* src = reinterpret_cast<const uint4*>(g_Ed + (size_t)b * (NN * EDP));
        uint4* dst = reinterpret_cast<uint4*>(ed);
        for (int i = tid; i < (NN * EDP) / 4; i += 512) dst[i] = src[i];
    }
    __syncthreads();

    // symmetric GEMM: 43 strips of 4 -> 946 unordered strip pairs (si >= sj)
    const float scale = 0.08838834764831843f;              // 1/sqrt(128)
    for (int cell = tid; cell < 946; cell += 512) {
        int si = (int)((sqrtf(8.0f * (float)cell + 1.0f) - 1.0f) * 0.5f);
        while ((si + 1) * (si + 2) / 2 <= cell) si++;
        while (si * (si + 1) / 2 > cell) si--;
        const int sj = cell - si * (si + 1) / 2;
        const int n = si * 4, k = sj * 4;                  // n,k <= 168

        u64t acc[4][2];
        #pragma unroll
        for (int i = 0; i < 4; i++) { acc[i][0] = 0ull; acc[i][1] = 0ull; }

        const float* ap = ed + n;
        const float* bp = ed + k;
        #pragma unroll 2
        for (int m = 0; m < NN; m++) {
            float4 a4 = *reinterpret_cast<const float4*>(ap + m * EDP);
            ulonglong2 b2 = *reinterpret_cast<const ulonglong2*>(bp + m * EDP);
            u64t s0 = splat2(a4.x), s1 = splat2(a4.y),
                 s2 = splat2(a4.z), s3 = splat2(a4.w);
            ffma2(acc[0][0], s0, b2.x); ffma2(acc[0][1], s0, b2.y);
            ffma2(acc[1][0], s1, b2.x); ffma2(acc[1][1], s1, b2.y);
            ffma2(acc[2][0], s2, b2.x); ffma2(acc[2][1], s2, b2.y);
            ffma2(acc[3][0], s3, b2.x); ffma2(acc[3][1], s3, b2.y);
        }

        #pragma unroll
        for (int i = 0; i < 4; i++) {
            int nn = n + i;
            if (nn >= NN) continue;
            float av[4];
            unpack2(av[0], av[1], acc[i][0]);
            unpack2(av[2], av[3], acc[i][1]);
            #pragma unroll
            for (int j = 0; j < 4; j++) {
                int kk = k + j;
                if (kk >= NN) continue;
                float s = fmaxf(0.0f, av[j] * scale);
                __nv_bfloat16 hv = __float2bfloat16(s);
                sc[nn * EDP + kk] = hv;
                sc[kk * EDP + nn] = hv;                    // mirror (diag: same)
            }
        }
    }
    __syncthreads();

    // row softmax (scores in [0,~15.1] -> no max pass) + atomic accumulate
    const int wid = tid >> 5, lane = tid & 31;
    for (int n = wid; n < NN; n += 16) {
        const __nv_bfloat16* row = sc + n * EDP;
        float ssum = 0.0f;
        for (int k = lane; k < NN; k += 32)
            ssum += __expf(__bfloat162float(row[k]));
        #pragma unroll
        for (int o = 16; o; o >>= 1)
            ssum += __shfl_xor_sync(0xffffffffu, ssum, o);
        float inv = 1.0f / ssum;
        for (int k = lane; k < NN; k += 32)
            atomicAdd(&g_Asum[n * NN + k],
                      __expf(__bfloat162float(row[k])) * inv);
    }
}

// --------------------------------- K3: threshold + self-restore (zero g_Asum)
__global__ void k_thresh(float* __restrict__ out) {
    int i = blockIdx.x * blockDim.x + threadIdx.x;
    if (i < NN * NN) {
        out[i] = (g_Asum[i] > 64.0f) ? 1.0f : 0.0f;        // mean > 0.5
        g_Asum[i] = 0.0f;                                  // restore for replay
    }
}

// ------------------------------------------------------------------- launcher
extern "C" void kernel_launch(void* const* d_in, const int* in_sizes, int n_in,
                              void* d_out, int out_size) {
    const float* x  = (const float*)d_in[0];   // [128,128,170,12] f32
    const float* Es = (const float*)d_in[1];   // [128,170] f32
    float* out = (float*)d_out;                // [170,170] f32

    cudaFuncSetAttribute(k_embed, cudaFuncAttributeMaxDynamicSharedMemorySize, SMEM_E);
    cudaFuncSetAttribute(k_adj,   cudaFuncAttributeMaxDynamicSharedMemorySize, SMEM_A);

    dim3 ge(BATCH, 2);
    k_embed<<<ge, 256, SMEM_E>>>(x, Es);
    k_adj<<<BATCH, 512, SMEM_A>>>();
    k_thresh<<<(NN * NN + 255) / 256, 256>>>(out);
}